// round 7
// baseline (speedup 1.0000x reference)
#include <cuda_runtime.h>
#include <cuda_bf16.h>
#include <cstdint>
#include <cstring>

#define DD 128
#define NPAD 50048
#define GMAXC 64
#define EMAX 1600000
#define SA 136                 // smem row stride in halves (68 u32)

// ---- scratch (device globals; no allocation allowed) ----
__device__ float g_Xd  [(size_t)NPAD * DD];
__device__ float g_Xc  [(size_t)NPAD * DD];
__device__ float g_self[(size_t)NPAD * DD];
__device__ float g_bufA[(size_t)NPAD * DD];
__device__ float g_bufB[(size_t)NPAD * DD];
__device__ float g_cnt[GMAXC];

// CSR scratch
__device__ int g_deg [NPAD + 1];
__device__ int g_off [NPAD + 1];
__device__ int g_cur [NPAD];
__device__ int g_adj [EMAX];          // packed: src | (type<<31)
__device__ int g_bsum[256];

// bf16-split weight images, transposed [n][k], PAIR-PACKED u32 slots:
// within each 16-col k-group, u32 pair q (cols 2q,2q+1) stored at slot
// (q%4)*2 + q/4  -> fragment words (k=cc, k=cc+8) are adjacent (LDS.64)
__device__ uint32_t g_Wh[9][8192];
__device__ uint32_t g_Wl[9][8192];

__device__ __forceinline__ int pack_slot(int q /*0..63 col-pair*/) {
    int ks = q >> 3, qq = q & 7;
    return ks * 8 + (qq & 3) * 2 + (qq >> 2);
}

// ============================================================
// Weight prep
// ============================================================
__global__ void prep_w_kernel(const float* __restrict__ Wd,
                              const float* __restrict__ Wc,
                              const float* __restrict__ Ws)
{
    int img = blockIdx.x;
    int layer = img / 3, f = img % 3;
    const float* W = ((f == 0) ? Wd : (f == 1) ? Wc : Ws) + (size_t)layer * DD * DD;
    int n = threadIdx.x;

    uint32_t* Hi = g_Wh[img];
    uint32_t* Lo = g_Wl[img];

    for (int q = 0; q < 64; q++) {
        int k = q * 2;
        float x0 = W[(size_t)k * DD + n];
        float x1 = W[(size_t)(k + 1) * DD + n];
        __nv_bfloat162 h = __floats2bfloat162_rn(x0, x1);
        float2 hf = __bfloat1622float2(h);
        __nv_bfloat162 l = __floats2bfloat162_rn(x0 - hf.x, x1 - hf.y);
        uint32_t hp, lp;
        memcpy(&hp, &h, 4); memcpy(&lp, &l, 4);
        int s = pack_slot(q);
        Hi[n * 64 + s] = hp;
        Lo[n * 64 + s] = lp;
    }
}

// ============================================================
// mma.sync bf16 GEMM (R5 structure + pair-packed LDS.64 operands)
// ============================================================
#define MMA_BF16(c, a0, a1, a2, a3, b0, b1)                                    \
    asm volatile("mma.sync.aligned.m16n8k16.row.col.f32.bf16.bf16.f32 "        \
                 "{%0,%1,%2,%3}, {%4,%5,%6,%7}, {%8,%9}, {%0,%1,%2,%3};"       \
                 : "+f"(c[0]), "+f"(c[1]), "+f"(c[2]), "+f"(c[3])              \
                 : "r"(a0), "r"(a1), "r"(a2), "r"(a3), "r"(b0), "r"(b1))

#define SM_BIAS 0
#define SM_AH   1536
#define SM_AL   (SM_AH + 128 * SA * 2)
#define SM_BH   (SM_AL + 128 * SA * 2)
#define SM_BL   (SM_BH + 128 * SA * 2)
#define SM_GTOT (SM_BL + 128 * SA * 2)   // 140800

__device__ __forceinline__ void copy_b(__nv_bfloat16* B, const uint32_t* src, int tid) {
    const uint4* s = (const uint4*)src;
    for (int i = tid; i < 2048; i += 256) {
        int rr = i >> 4, c16 = i & 15;
        *(uint4*)&B[rr * SA + c16 * 8] = s[i];
    }
}

__global__ __launch_bounds__(256, 1) void gemm_mma_kernel(
    const float* __restrict__ Xext, int in_sel, int layer,
    const float* __restrict__ bd, const float* __restrict__ bc,
    const float* __restrict__ bs, int N)
{
    extern __shared__ char smem[];
    float* bias_s = (float*)(smem + SM_BIAS);
    __nv_bfloat16* Ah = (__nv_bfloat16*)(smem + SM_AH);
    __nv_bfloat16* Al = (__nv_bfloat16*)(smem + SM_AL);
    __nv_bfloat16* Bh = (__nv_bfloat16*)(smem + SM_BH);
    __nv_bfloat16* Bl = (__nv_bfloat16*)(smem + SM_BL);

    const int tid = threadIdx.x, wid = tid >> 5, lane = tid & 31;
    const float* Xin = (in_sel == 0) ? Xext : ((in_sel == 1) ? g_bufA : g_bufB);
    const int row0 = blockIdx.x * 128;

    if (tid < 128) {
        bias_s[tid]       = bd[layer * DD + tid];
        bias_s[128 + tid] = bc[layer * DD + tid];
        bias_s[256 + tid] = bs[layer * DD + tid];
    }

    // ---- A conversion: fp32 -> bf16 hi/lo, pair-packed slots ----
    {
        int r  = tid >> 1;
        int c0 = (tid & 1) * 64;          // starting column (64 cols per half)
        int gr = row0 + r;
        bool ok = gr < N;
        const float4* xp = (const float4*)(Xin + (size_t)gr * DD + c0);
        uint32_t* ah = (uint32_t*)&Ah[r * SA];
        uint32_t* al = (uint32_t*)&Al[r * SA];
#pragma unroll
        for (int c4 = 0; c4 < 16; c4++) {
            float4 v = ok ? __ldg(xp + c4) : make_float4(0.f, 0.f, 0.f, 0.f);
            __nv_bfloat162 h01 = __floats2bfloat162_rn(v.x, v.y);
            __nv_bfloat162 h23 = __floats2bfloat162_rn(v.z, v.w);
            float2 f01 = __bfloat1622float2(h01);
            float2 f23 = __bfloat1622float2(h23);
            __nv_bfloat162 l01 = __floats2bfloat162_rn(v.x - f01.x, v.y - f01.y);
            __nv_bfloat162 l23 = __floats2bfloat162_rn(v.z - f23.x, v.w - f23.y);
            uint32_t hp0, hp1, lp0, lp1;
            memcpy(&hp0, &h01, 4); memcpy(&hp1, &h23, 4);
            memcpy(&lp0, &l01, 4); memcpy(&lp1, &l23, 4);
            int q0 = (c0 + c4 * 4) >> 1;       // col pair of (v.x,v.y)
            int s0 = pack_slot(q0);
            int s1 = pack_slot(q0 + 1);
            ah[s0] = hp0; ah[s1] = hp1;
            al[s0] = lp0; al[s1] = lp1;
        }
    }

    const int mrow = wid * 16;
    const int r    = lane >> 2;
    const int qq   = lane & 3;            // col-pair index within k-group

    const uint32_t* arow0h = (const uint32_t*)&Ah[(mrow + r) * SA];
    const uint32_t* arow1h = (const uint32_t*)&Ah[(mrow + r + 8) * SA];
    const uint32_t* arow0l = (const uint32_t*)&Al[(mrow + r) * SA];
    const uint32_t* arow1l = (const uint32_t*)&Al[(mrow + r + 8) * SA];

    for (int f = 0; f < 3; f++) {
        __syncthreads();                          // prior readers of B done
        copy_b(Bh, g_Wh[layer * 3 + f], tid);
        copy_b(Bl, g_Wl[layer * 3 + f], tid);
        __syncthreads();

        float acc[16][4];
#pragma unroll
        for (int nt = 0; nt < 16; nt++)
#pragma unroll
            for (int q = 0; q < 4; q++) acc[nt][q] = 0.f;

#pragma unroll
        for (int ks = 0; ks < 8; ks++) {
            const int sl = ks * 8 + qq * 2;       // u32 slot of (k=cc | k=cc+8) pair
            uint2 a02h = *(const uint2*)(arow0h + sl);
            uint2 a13h = *(const uint2*)(arow1h + sl);
            uint2 a02l = *(const uint2*)(arow0l + sl);
            uint2 a13l = *(const uint2*)(arow1l + sl);
#pragma unroll
            for (int nt = 0; nt < 16; nt++) {
                const uint32_t* brow = (const uint32_t*)&Bh[(nt * 8 + r) * SA];
                const uint32_t* browl = (const uint32_t*)&Bl[(nt * 8 + r) * SA];
                uint2 bh = *(const uint2*)(brow + sl);
                uint2 bl = *(const uint2*)(browl + sl);
                MMA_BF16(acc[nt], a02h.x, a13h.x, a02h.y, a13h.y, bh.x, bh.y);
                MMA_BF16(acc[nt], a02l.x, a13l.x, a02l.y, a13l.y, bh.x, bh.y);
                MMA_BF16(acc[nt], a02h.x, a13h.x, a02h.y, a13h.y, bl.x, bl.y);
            }
        }

        // epilogue: +bias, float2 stores
        float* out = (f == 0) ? g_Xd : ((f == 1) ? g_Xc : g_self);
        const float* bv = bias_s + f * 128;
        const int cc = qq * 2;
        int gr0 = row0 + mrow + r;
        int gr1 = gr0 + 8;
#pragma unroll
        for (int nt = 0; nt < 16; nt++) {
            int col = nt * 8 + cc;
            float bx = bv[col], by = bv[col + 1];
            if (gr0 < N)
                *(float2*)(out + (size_t)gr0 * DD + col) =
                    make_float2(acc[nt][0] + bx, acc[nt][1] + by);
            if (gr1 < N)
                *(float2*)(out + (size_t)gr1 * DD + col) =
                    make_float2(acc[nt][2] + bx, acc[nt][3] + by);
        }
    }
}

// ============================================================
// CSR build
// ============================================================
__global__ void zero_deg_kernel(int N)
{
    int i = blockIdx.x * blockDim.x + threadIdx.x;
    if (i <= N) g_deg[i] = 0;
}

__global__ void hist_kernel(const int* __restrict__ ei, int E)
{
    int e = blockIdx.x * blockDim.x + threadIdx.x;
    if (e < E) atomicAdd(&g_deg[ei[E + e]], 1);
}

__global__ void scan1_kernel(int N)
{
    __shared__ int s[256];
    int tid = threadIdx.x;
    int i = blockIdx.x * 256 + tid;
    int v = (i < N) ? g_deg[i] : 0;
    s[tid] = v;
    __syncthreads();
#pragma unroll
    for (int o = 1; o < 256; o <<= 1) {
        int t = (tid >= o) ? s[tid - o] : 0;
        __syncthreads();
        s[tid] += t;
        __syncthreads();
    }
    if (i < N) g_off[i] = s[tid] - v;
    if (tid == 255) g_bsum[blockIdx.x] = s[255];
}

__global__ void scan2_kernel(int nb)
{
    __shared__ int s[256];
    int tid = threadIdx.x;
    int v = (tid < nb) ? g_bsum[tid] : 0;
    s[tid] = v;
    __syncthreads();
#pragma unroll
    for (int o = 1; o < 256; o <<= 1) {
        int t = (tid >= o) ? s[tid - o] : 0;
        __syncthreads();
        s[tid] += t;
        __syncthreads();
    }
    if (tid < nb) g_bsum[tid] = s[tid] - v;
}

__global__ void scan3_kernel(int N, int E)
{
    int i = blockIdx.x * blockDim.x + threadIdx.x;
    if (i < N) {
        int o = g_off[i] + g_bsum[i >> 8];
        g_off[i] = o;
        g_cur[i] = o;
    }
    if (i == 0) g_off[N] = E;
}

__global__ void scatter_kernel(const int* __restrict__ ei,
                               const int* __restrict__ et, int E)
{
    int e = blockIdx.x * blockDim.x + threadIdx.x;
    if (e >= E) return;
    int src = ei[e];
    int dst = ei[E + e];
    int t   = et[e];
    int pos = atomicAdd(&g_cur[dst], 1);
    g_adj[pos] = src | (t << 31);
}

// ============================================================
// Aggregation (gather-only): one warp per dst node, MLP=8.
// pool=1: relu result red.add'ed into pool output instead of buffer.
// ============================================================
__global__ __launch_bounds__(256) void agg_kernel(
    int N, int out_sel, int pool,
    const int* __restrict__ batch_ids, float* __restrict__ pout)
{
    int node = blockIdx.x * 8 + (threadIdx.x >> 5);
    int lane = threadIdx.x & 31;
    if (node >= N) return;

    int beg = g_off[node];
    int end = g_off[node + 1];

    float4 acc = *(const float4*)(g_self + (size_t)node * DD + lane * 4);

    for (int base = beg; base < end; base += 32) {
        int cnt = end - base; if (cnt > 32) cnt = 32;
        int idx = (base + lane < end) ? g_adj[base + lane] : 0;
        int q = 0;
        for (; q + 8 <= cnt; q += 8) {
            float4 v[8];
#pragma unroll
            for (int u = 0; u < 8; u++) {
                int p = __shfl_sync(0xffffffffu, idx, q + u);
                const float* bp = (p < 0) ? g_Xc : g_Xd;
                v[u] = *(const float4*)(bp + (size_t)(p & 0x7fffffff) * DD + lane * 4);
            }
#pragma unroll
            for (int u = 0; u < 8; u++) {
                acc.x += v[u].x; acc.y += v[u].y;
                acc.z += v[u].z; acc.w += v[u].w;
            }
        }
        for (; q + 4 <= cnt; q += 4) {
            float4 v[4];
#pragma unroll
            for (int u = 0; u < 4; u++) {
                int p = __shfl_sync(0xffffffffu, idx, q + u);
                const float* bp = (p < 0) ? g_Xc : g_Xd;
                v[u] = *(const float4*)(bp + (size_t)(p & 0x7fffffff) * DD + lane * 4);
            }
#pragma unroll
            for (int u = 0; u < 4; u++) {
                acc.x += v[u].x; acc.y += v[u].y;
                acc.z += v[u].z; acc.w += v[u].w;
            }
        }
        for (; q < cnt; q++) {
            int p = __shfl_sync(0xffffffffu, idx, q);
            const float* bp = (p < 0) ? g_Xc : g_Xd;
            float4 v = *(const float4*)(bp + (size_t)(p & 0x7fffffff) * DD + lane * 4);
            acc.x += v.x; acc.y += v.y; acc.z += v.z; acc.w += v.w;
        }
    }

    acc.x = fmaxf(acc.x, 0.f); acc.y = fmaxf(acc.y, 0.f);
    acc.z = fmaxf(acc.z, 0.f); acc.w = fmaxf(acc.w, 0.f);

    if (pool) {
        int b = batch_ids[node];
        float* dp = pout + (size_t)b * DD + lane * 4;
        asm volatile("red.global.add.v4.f32 [%0], {%1,%2,%3,%4};"
                     :: "l"(dp), "f"(acc.x), "f"(acc.y), "f"(acc.z), "f"(acc.w)
                     : "memory");
    } else {
        float* out = (out_sel == 0) ? g_bufA : g_bufB;
        *(float4*)(out + (size_t)node * DD + lane * 4) = acc;
    }
}

// ============================================================
// Pooling support
// ============================================================
__global__ void zero_kernel(float* __restrict__ out, int out_size, int G)
{
    int i = blockIdx.x * blockDim.x + threadIdx.x;
    if (i < out_size) out[i] = 0.f;
    if (i < G) g_cnt[i] = 0.f;
}

__global__ void cnt_kernel(const int* __restrict__ batch_ids, int N)
{
    int i = blockIdx.x * blockDim.x + threadIdx.x;
    if (i < N) atomicAdd(&g_cnt[batch_ids[i]], 1.0f);
}

__global__ void pool_div_kernel(float* __restrict__ out, int out_size)
{
    int i = blockIdx.x * blockDim.x + threadIdx.x;
    if (i >= out_size) return;
    out[i] = out[i] / fmaxf(g_cnt[i >> 7], 1.0f);
}

// ============================================================
// launch
// ============================================================
extern "C" void kernel_launch(void* const* d_in, const int* in_sizes, int n_in,
                              void* d_out, int out_size)
{
    const float* X   = (const float*)d_in[0];
    const float* Wd  = (const float*)d_in[1];
    const float* bd  = (const float*)d_in[2];
    const float* Wc  = (const float*)d_in[3];
    const float* bc  = (const float*)d_in[4];
    const float* Ws  = (const float*)d_in[5];
    const float* bs  = (const float*)d_in[6];
    const int*   ei  = (const int*)d_in[7];
    const int*   et  = (const int*)d_in[8];
    const int*   bid = (const int*)d_in[9];
    float* out = (float*)d_out;

    const int N = in_sizes[0] / DD;
    const int E = in_sizes[8];
    const int G = out_size / DD;

    static bool attr_done = false;
    if (!attr_done) {
        cudaFuncSetAttribute(gemm_mma_kernel,
                             cudaFuncAttributeMaxDynamicSharedMemorySize, SM_GTOT);
        attr_done = true;
    }

    int gtiles = (N + 127) / 128;
    int eblk  = (E + 255) / 256;
    int nwarp = (N + 7) / 8;
    int nb    = (N + 255) / 256;

    // ---- weight prep + CSR build + pool init ----
    prep_w_kernel<<<9, 128>>>(Wd, Wc, Ws);
    zero_deg_kernel<<<(N + 256) / 256, 256>>>(N);
    hist_kernel<<<eblk, 256>>>(ei, E);
    scan1_kernel<<<nb, 256>>>(N);
    scan2_kernel<<<1, 256>>>(nb);
    scan3_kernel<<<nb, 256>>>(N, E);
    scatter_kernel<<<eblk, 256>>>(ei, et, E);
    zero_kernel<<<(out_size + G + 255) / 256, 256>>>(out, out_size, G);
    cnt_kernel<<<nb, 256>>>(bid, N);

    // ---- layers ----
    gemm_mma_kernel<<<gtiles, 256, SM_GTOT>>>(X, 0, 0, bd, bc, bs, N);
    agg_kernel<<<nwarp, 256>>>(N, 0, 0, bid, out);    // -> bufA

    gemm_mma_kernel<<<gtiles, 256, SM_GTOT>>>(X, 1, 1, bd, bc, bs, N);
    agg_kernel<<<nwarp, 256>>>(N, 1, 0, bid, out);    // -> bufB

    gemm_mma_kernel<<<gtiles, 256, SM_GTOT>>>(X, 2, 2, bd, bc, bs, N);
    agg_kernel<<<nwarp, 256>>>(N, 0, 1, bid, out);    // -> pooled into out

    pool_div_kernel<<<(out_size + 255) / 256, 256>>>(out, out_size);
}

// round 8
// speedup vs baseline: 1.0827x; 1.0827x over previous
#include <cuda_runtime.h>
#include <cuda_bf16.h>
#include <cstdint>
#include <cstring>

#define DD 128
#define NPAD 50048
#define GMAXC 64
#define EMAX 1600000
#define SA 136                 // smem row stride in halves (conflict-free layout)

// ---- scratch (device globals; no allocation allowed) ----
__device__ float g_Xd  [(size_t)NPAD * DD];
__device__ float g_Xc  [(size_t)NPAD * DD];
__device__ float g_self[(size_t)NPAD * DD];
__device__ float g_bufA[(size_t)NPAD * DD];
__device__ float g_bufB[(size_t)NPAD * DD];
__device__ float g_cnt[GMAXC];

// CSR scratch
__device__ int g_deg [NPAD + 1];
__device__ int g_off [NPAD + 1];
__device__ int g_cur [NPAD];
__device__ int g_adj [EMAX];          // packed: src | (type<<31)
__device__ int g_bsum[256];

// bf16-split weight images, TRANSPOSED [n][k], packed as u32 (k, k+1) pairs
__device__ uint32_t g_Wh[9][8192];
__device__ uint32_t g_Wl[9][8192];

// ============================================================
// Weight prep
// ============================================================
__global__ void prep_w_kernel(const float* __restrict__ Wd,
                              const float* __restrict__ Wc,
                              const float* __restrict__ Ws)
{
    int img = blockIdx.x;
    int layer = img / 3, f = img % 3;
    const float* W = ((f == 0) ? Wd : (f == 1) ? Wc : Ws) + (size_t)layer * DD * DD;
    int n = threadIdx.x;

    uint32_t* Hi = g_Wh[img];
    uint32_t* Lo = g_Wl[img];

    for (int k = 0; k < DD; k += 2) {
        float x0 = W[(size_t)k * DD + n];
        float x1 = W[(size_t)(k + 1) * DD + n];
        __nv_bfloat162 h = __floats2bfloat162_rn(x0, x1);
        float2 hf = __bfloat1622float2(h);
        __nv_bfloat162 l = __floats2bfloat162_rn(x0 - hf.x, x1 - hf.y);
        uint32_t hp, lp;
        memcpy(&hp, &h, 4); memcpy(&lp, &l, 4);
        Hi[n * 64 + (k >> 1)] = hp;
        Lo[n * 64 + (k >> 1)] = lp;
    }
}

// ============================================================
// mma.sync bf16 GEMM (R5 structure: conflict-free scalar LDS)
// ============================================================
#define MMA_BF16(c, a0, a1, a2, a3, b0, b1)                                    \
    asm volatile("mma.sync.aligned.m16n8k16.row.col.f32.bf16.bf16.f32 "        \
                 "{%0,%1,%2,%3}, {%4,%5,%6,%7}, {%8,%9}, {%0,%1,%2,%3};"       \
                 : "+f"(c[0]), "+f"(c[1]), "+f"(c[2]), "+f"(c[3])              \
                 : "r"(a0), "r"(a1), "r"(a2), "r"(a3), "r"(b0), "r"(b1))

#define SM_BIAS 0
#define SM_AH   1536
#define SM_AL   (SM_AH + 128 * SA * 2)
#define SM_BH   (SM_AL + 128 * SA * 2)
#define SM_BL   (SM_BH + 128 * SA * 2)
#define SM_GTOT (SM_BL + 128 * SA * 2)   // 140800

__device__ __forceinline__ void copy_b(__nv_bfloat16* B, const uint32_t* src, int tid) {
    const uint4* s = (const uint4*)src;
    for (int i = tid; i < 2048; i += 256) {
        int rr = i >> 4, c16 = i & 15;
        *(uint4*)&B[rr * SA + c16 * 8] = s[i];
    }
}

__global__ __launch_bounds__(256, 1) void gemm_mma_kernel(
    const float* __restrict__ Xext, int in_sel, int layer,
    const float* __restrict__ bd, const float* __restrict__ bc,
    const float* __restrict__ bs, int N)
{
    extern __shared__ char smem[];
    float* bias_s = (float*)(smem + SM_BIAS);
    __nv_bfloat16* Ah = (__nv_bfloat16*)(smem + SM_AH);
    __nv_bfloat16* Al = (__nv_bfloat16*)(smem + SM_AL);
    __nv_bfloat16* Bh = (__nv_bfloat16*)(smem + SM_BH);
    __nv_bfloat16* Bl = (__nv_bfloat16*)(smem + SM_BL);

    const int tid = threadIdx.x, wid = tid >> 5, lane = tid & 31;
    const float* Xin = (in_sel == 0) ? Xext : ((in_sel == 1) ? g_bufA : g_bufB);
    const int row0 = blockIdx.x * 128;

    if (tid < 128) {
        bias_s[tid]       = bd[layer * DD + tid];
        bias_s[128 + tid] = bc[layer * DD + tid];
        bias_s[256 + tid] = bs[layer * DD + tid];
    }

    // ---- A conversion: fp32 -> bf16 hi/lo ----
    {
        int r  = tid >> 1;
        int c0 = (tid & 1) * 64;
        int gr = row0 + r;
        bool ok = gr < N;
        const float4* xp = (const float4*)(Xin + (size_t)gr * DD + c0);
        uint32_t* ah = (uint32_t*)&Ah[r * SA + c0];
        uint32_t* al = (uint32_t*)&Al[r * SA + c0];
#pragma unroll
        for (int c4 = 0; c4 < 16; c4++) {
            float4 v = ok ? __ldg(xp + c4) : make_float4(0.f, 0.f, 0.f, 0.f);
            __nv_bfloat162 h01 = __floats2bfloat162_rn(v.x, v.y);
            __nv_bfloat162 h23 = __floats2bfloat162_rn(v.z, v.w);
            float2 f01 = __bfloat1622float2(h01);
            float2 f23 = __bfloat1622float2(h23);
            __nv_bfloat162 l01 = __floats2bfloat162_rn(v.x - f01.x, v.y - f01.y);
            __nv_bfloat162 l23 = __floats2bfloat162_rn(v.z - f23.x, v.w - f23.y);
            uint32_t hp0, hp1, lp0, lp1;
            memcpy(&hp0, &h01, 4); memcpy(&hp1, &h23, 4);
            memcpy(&lp0, &l01, 4); memcpy(&lp1, &l23, 4);
            ah[c4 * 2] = hp0; ah[c4 * 2 + 1] = hp1;
            al[c4 * 2] = lp0; al[c4 * 2 + 1] = lp1;
        }
    }

    const int mrow = wid * 16;
    const int r    = lane >> 2;
    const int cc   = (lane & 3) * 2;

    for (int f = 0; f < 3; f++) {
        __syncthreads();                          // prior readers of B done
        copy_b(Bh, g_Wh[layer * 3 + f], tid);
        copy_b(Bl, g_Wl[layer * 3 + f], tid);
        __syncthreads();

        float acc[16][4];
#pragma unroll
        for (int nt = 0; nt < 16; nt++)
#pragma unroll
            for (int q = 0; q < 4; q++) acc[nt][q] = 0.f;

#pragma unroll
        for (int ks = 0; ks < 8; ks++) {
            const int kb = ks * 16;
            uint32_t a0h = *(const uint32_t*)&Ah[(mrow + r)     * SA + kb + cc];
            uint32_t a1h = *(const uint32_t*)&Ah[(mrow + r + 8) * SA + kb + cc];
            uint32_t a2h = *(const uint32_t*)&Ah[(mrow + r)     * SA + kb + cc + 8];
            uint32_t a3h = *(const uint32_t*)&Ah[(mrow + r + 8) * SA + kb + cc + 8];
            uint32_t a0l = *(const uint32_t*)&Al[(mrow + r)     * SA + kb + cc];
            uint32_t a1l = *(const uint32_t*)&Al[(mrow + r + 8) * SA + kb + cc];
            uint32_t a2l = *(const uint32_t*)&Al[(mrow + r)     * SA + kb + cc + 8];
            uint32_t a3l = *(const uint32_t*)&Al[(mrow + r + 8) * SA + kb + cc + 8];
#pragma unroll
            for (int nt = 0; nt < 16; nt++) {
                const int nb = (nt * 8 + r) * SA + kb + cc;
                uint32_t b0h = *(const uint32_t*)&Bh[nb];
                uint32_t b1h = *(const uint32_t*)&Bh[nb + 8];
                uint32_t b0l = *(const uint32_t*)&Bl[nb];
                uint32_t b1l = *(const uint32_t*)&Bl[nb + 8];
                MMA_BF16(acc[nt], a0h, a1h, a2h, a3h, b0h, b1h);
                MMA_BF16(acc[nt], a0h, a1h, a2h, a3h, b0l, b1l);
                MMA_BF16(acc[nt], a0l, a1l, a2l, a3l, b0h, b1h);
            }
        }

        // epilogue: +bias, float2 stores
        float* out = (f == 0) ? g_Xd : ((f == 1) ? g_Xc : g_self);
        const float* bv = bias_s + f * 128;
        int gr0 = row0 + mrow + r;
        int gr1 = gr0 + 8;
#pragma unroll
        for (int nt = 0; nt < 16; nt++) {
            int col = nt * 8 + cc;
            float bx = bv[col], by = bv[col + 1];
            if (gr0 < N)
                *(float2*)(out + (size_t)gr0 * DD + col) =
                    make_float2(acc[nt][0] + bx, acc[nt][1] + by);
            if (gr1 < N)
                *(float2*)(out + (size_t)gr1 * DD + col) =
                    make_float2(acc[nt][2] + bx, acc[nt][3] + by);
        }
    }
}

// ============================================================
// CSR build
// ============================================================
__global__ void zero_deg_kernel(int N)
{
    int i = blockIdx.x * blockDim.x + threadIdx.x;
    if (i <= N) g_deg[i] = 0;
}

__global__ void hist_kernel(const int* __restrict__ ei, int E)
{
    int e = blockIdx.x * blockDim.x + threadIdx.x;
    if (e < E) atomicAdd(&g_deg[ei[E + e]], 1);
}

__global__ void scan1_kernel(int N)
{
    __shared__ int s[256];
    int tid = threadIdx.x;
    int i = blockIdx.x * 256 + tid;
    int v = (i < N) ? g_deg[i] : 0;
    s[tid] = v;
    __syncthreads();
#pragma unroll
    for (int o = 1; o < 256; o <<= 1) {
        int t = (tid >= o) ? s[tid - o] : 0;
        __syncthreads();
        s[tid] += t;
        __syncthreads();
    }
    if (i < N) g_off[i] = s[tid] - v;
    if (tid == 255) g_bsum[blockIdx.x] = s[255];
}

__global__ void scan2_kernel(int nb)
{
    __shared__ int s[256];
    int tid = threadIdx.x;
    int v = (tid < nb) ? g_bsum[tid] : 0;
    s[tid] = v;
    __syncthreads();
#pragma unroll
    for (int o = 1; o < 256; o <<= 1) {
        int t = (tid >= o) ? s[tid - o] : 0;
        __syncthreads();
        s[tid] += t;
        __syncthreads();
    }
    if (tid < nb) g_bsum[tid] = s[tid] - v;
}

__global__ void scan3_kernel(int N, int E)
{
    int i = blockIdx.x * blockDim.x + threadIdx.x;
    if (i < N) {
        int o = g_off[i] + g_bsum[i >> 8];
        g_off[i] = o;
        g_cur[i] = o;
    }
    if (i == 0) g_off[N] = E;
}

__global__ void scatter_kernel(const int* __restrict__ ei,
                               const int* __restrict__ et, int E)
{
    int e = blockIdx.x * blockDim.x + threadIdx.x;
    if (e >= E) return;
    int src = ei[e];
    int dst = ei[E + e];
    int t   = et[e];
    int pos = atomicAdd(&g_cur[dst], 1);
    g_adj[pos] = src | (t << 31);
}

// ============================================================
// Aggregation (gather-only): one warp per dst node, MLP=8.
// pool=1: relu result red.add'ed into pool output instead of buffer.
// ============================================================
__global__ __launch_bounds__(256) void agg_kernel(
    int N, int out_sel, int pool,
    const int* __restrict__ batch_ids, float* __restrict__ pout)
{
    int node = blockIdx.x * 8 + (threadIdx.x >> 5);
    int lane = threadIdx.x & 31;
    if (node >= N) return;

    int beg = g_off[node];
    int end = g_off[node + 1];

    float4 acc = *(const float4*)(g_self + (size_t)node * DD + lane * 4);

    for (int base = beg; base < end; base += 32) {
        int cnt = end - base; if (cnt > 32) cnt = 32;
        int idx = (base + lane < end) ? g_adj[base + lane] : 0;
        int q = 0;
        for (; q + 8 <= cnt; q += 8) {
            float4 v[8];
#pragma unroll
            for (int u = 0; u < 8; u++) {
                int p = __shfl_sync(0xffffffffu, idx, q + u);
                const float* bp = (p < 0) ? g_Xc : g_Xd;
                v[u] = *(const float4*)(bp + (size_t)(p & 0x7fffffff) * DD + lane * 4);
            }
#pragma unroll
            for (int u = 0; u < 8; u++) {
                acc.x += v[u].x; acc.y += v[u].y;
                acc.z += v[u].z; acc.w += v[u].w;
            }
        }
        for (; q + 4 <= cnt; q += 4) {
            float4 v[4];
#pragma unroll
            for (int u = 0; u < 4; u++) {
                int p = __shfl_sync(0xffffffffu, idx, q + u);
                const float* bp = (p < 0) ? g_Xc : g_Xd;
                v[u] = *(const float4*)(bp + (size_t)(p & 0x7fffffff) * DD + lane * 4);
            }
#pragma unroll
            for (int u = 0; u < 4; u++) {
                acc.x += v[u].x; acc.y += v[u].y;
                acc.z += v[u].z; acc.w += v[u].w;
            }
        }
        for (; q < cnt; q++) {
            int p = __shfl_sync(0xffffffffu, idx, q);
            const float* bp = (p < 0) ? g_Xc : g_Xd;
            float4 v = *(const float4*)(bp + (size_t)(p & 0x7fffffff) * DD + lane * 4);
            acc.x += v.x; acc.y += v.y; acc.z += v.z; acc.w += v.w;
        }
    }

    acc.x = fmaxf(acc.x, 0.f); acc.y = fmaxf(acc.y, 0.f);
    acc.z = fmaxf(acc.z, 0.f); acc.w = fmaxf(acc.w, 0.f);

    if (pool) {
        int b = batch_ids[node];
        float* dp = pout + (size_t)b * DD + lane * 4;
        asm volatile("red.global.add.v4.f32 [%0], {%1,%2,%3,%4};"
                     :: "l"(dp), "f"(acc.x), "f"(acc.y), "f"(acc.z), "f"(acc.w)
                     : "memory");
    } else {
        float* out = (out_sel == 0) ? g_bufA : g_bufB;
        *(float4*)(out + (size_t)node * DD + lane * 4) = acc;
    }
}

// ============================================================
// Pooling support
// ============================================================
__global__ void zero_kernel(float* __restrict__ out, int out_size, int G)
{
    int i = blockIdx.x * blockDim.x + threadIdx.x;
    if (i < out_size) out[i] = 0.f;
    if (i < G) g_cnt[i] = 0.f;
}

__global__ void cnt_kernel(const int* __restrict__ batch_ids, int N)
{
    int i = blockIdx.x * blockDim.x + threadIdx.x;
    if (i < N) atomicAdd(&g_cnt[batch_ids[i]], 1.0f);
}

__global__ void pool_div_kernel(float* __restrict__ out, int out_size)
{
    int i = blockIdx.x * blockDim.x + threadIdx.x;
    if (i >= out_size) return;
    out[i] = out[i] / fmaxf(g_cnt[i >> 7], 1.0f);
}

// ============================================================
// launch
// ============================================================
extern "C" void kernel_launch(void* const* d_in, const int* in_sizes, int n_in,
                              void* d_out, int out_size)
{
    const float* X   = (const float*)d_in[0];
    const float* Wd  = (const float*)d_in[1];
    const float* bd  = (const float*)d_in[2];
    const float* Wc  = (const float*)d_in[3];
    const float* bc  = (const float*)d_in[4];
    const float* Ws  = (const float*)d_in[5];
    const float* bs  = (const float*)d_in[6];
    const int*   ei  = (const int*)d_in[7];
    const int*   et  = (const int*)d_in[8];
    const int*   bid = (const int*)d_in[9];
    float* out = (float*)d_out;

    const int N = in_sizes[0] / DD;
    const int E = in_sizes[8];
    const int G = out_size / DD;

    static bool attr_done = false;
    if (!attr_done) {
        cudaFuncSetAttribute(gemm_mma_kernel,
                             cudaFuncAttributeMaxDynamicSharedMemorySize, SM_GTOT);
        attr_done = true;
    }

    int gtiles = (N + 127) / 128;
    int eblk  = (E + 255) / 256;
    int nwarp = (N + 7) / 8;
    int nb    = (N + 255) / 256;

    // ---- weight prep + CSR build + pool init ----
    prep_w_kernel<<<9, 128>>>(Wd, Wc, Ws);
    zero_deg_kernel<<<(N + 256) / 256, 256>>>(N);
    hist_kernel<<<eblk, 256>>>(ei, E);
    scan1_kernel<<<nb, 256>>>(N);
    scan2_kernel<<<1, 256>>>(nb);
    scan3_kernel<<<nb, 256>>>(N, E);
    scatter_kernel<<<eblk, 256>>>(ei, et, E);
    zero_kernel<<<(out_size + G + 255) / 256, 256>>>(out, out_size, G);
    cnt_kernel<<<nb, 256>>>(bid, N);

    // ---- layers ----
    gemm_mma_kernel<<<gtiles, 256, SM_GTOT>>>(X, 0, 0, bd, bc, bs, N);
    agg_kernel<<<nwarp, 256>>>(N, 0, 0, bid, out);    // -> bufA

    gemm_mma_kernel<<<gtiles, 256, SM_GTOT>>>(X, 1, 1, bd, bc, bs, N);
    agg_kernel<<<nwarp, 256>>>(N, 1, 0, bid, out);    // -> bufB

    gemm_mma_kernel<<<gtiles, 256, SM_GTOT>>>(X, 2, 2, bd, bc, bs, N);
    agg_kernel<<<nwarp, 256>>>(N, 0, 1, bid, out);    // -> pooled into out

    pool_div_kernel<<<(out_size + 255) / 256, 256>>>(out, out_size);
}

// round 9
// speedup vs baseline: 1.1054x; 1.0209x over previous
#include <cuda_runtime.h>
#include <cuda_bf16.h>
#include <cstdint>
#include <cstring>

#define DD 128
#define NPAD 50048
#define GMAXC 64
#define EMAX 1600000
#define SA 136                 // smem row stride in halves (conflict-free layout)

// ---- scratch (device globals; no allocation allowed) ----
__device__ float g_Xd  [(size_t)NPAD * DD];
__device__ float g_Xc  [(size_t)NPAD * DD];
__device__ float g_self[(size_t)NPAD * DD];
__device__ float g_bufA[(size_t)NPAD * DD];
__device__ float g_bufB[(size_t)NPAD * DD];
__device__ float g_cnt[GMAXC];

// CSR scratch
__device__ int g_deg [NPAD + 1];
__device__ int g_off [NPAD + 1];
__device__ int g_cur [NPAD];
__device__ int g_adj [EMAX];          // packed: src | (type<<31)
__device__ int g_bsum[256];

// bf16-split weight images, TRANSPOSED [n][k], packed as u32 (k, k+1) pairs
__device__ uint32_t g_Wh[9][8192];
__device__ uint32_t g_Wl[9][8192];

// ============================================================
// Weight prep
// ============================================================
__global__ void prep_w_kernel(const float* __restrict__ Wd,
                              const float* __restrict__ Wc,
                              const float* __restrict__ Ws)
{
    int img = blockIdx.x;
    int layer = img / 3, f = img % 3;
    const float* W = ((f == 0) ? Wd : (f == 1) ? Wc : Ws) + (size_t)layer * DD * DD;
    int n = threadIdx.x;

    uint32_t* Hi = g_Wh[img];
    uint32_t* Lo = g_Wl[img];

    for (int k = 0; k < DD; k += 2) {
        float x0 = W[(size_t)k * DD + n];
        float x1 = W[(size_t)(k + 1) * DD + n];
        __nv_bfloat162 h = __floats2bfloat162_rn(x0, x1);
        float2 hf = __bfloat1622float2(h);
        __nv_bfloat162 l = __floats2bfloat162_rn(x0 - hf.x, x1 - hf.y);
        uint32_t hp, lp;
        memcpy(&hp, &h, 4); memcpy(&lp, &l, 4);
        Hi[n * 64 + (k >> 1)] = hp;
        Lo[n * 64 + (k >> 1)] = lp;
    }
}

// ============================================================
// mma.sync bf16 GEMM (R5 structure: conflict-free scalar LDS)
// ============================================================
#define MMA_BF16(c, a0, a1, a2, a3, b0, b1)                                    \
    asm volatile("mma.sync.aligned.m16n8k16.row.col.f32.bf16.bf16.f32 "        \
                 "{%0,%1,%2,%3}, {%4,%5,%6,%7}, {%8,%9}, {%0,%1,%2,%3};"       \
                 : "+f"(c[0]), "+f"(c[1]), "+f"(c[2]), "+f"(c[3])              \
                 : "r"(a0), "r"(a1), "r"(a2), "r"(a3), "r"(b0), "r"(b1))

#define SM_BIAS 0
#define SM_AH   1536
#define SM_AL   (SM_AH + 128 * SA * 2)
#define SM_BH   (SM_AL + 128 * SA * 2)
#define SM_BL   (SM_BH + 128 * SA * 2)
#define SM_GTOT (SM_BL + 128 * SA * 2)   // 140800

__device__ __forceinline__ void copy_b(__nv_bfloat16* B, const uint32_t* src, int tid) {
    const uint4* s = (const uint4*)src;
    for (int i = tid; i < 2048; i += 256) {
        int rr = i >> 4, c16 = i & 15;
        *(uint4*)&B[rr * SA + c16 * 8] = s[i];
    }
}

__global__ __launch_bounds__(256, 1) void gemm_mma_kernel(
    const float* __restrict__ Xext, int in_sel, int layer,
    const float* __restrict__ bd, const float* __restrict__ bc,
    const float* __restrict__ bs, int N)
{
    extern __shared__ char smem[];
    float* bias_s = (float*)(smem + SM_BIAS);
    __nv_bfloat16* Ah = (__nv_bfloat16*)(smem + SM_AH);
    __nv_bfloat16* Al = (__nv_bfloat16*)(smem + SM_AL);
    __nv_bfloat16* Bh = (__nv_bfloat16*)(smem + SM_BH);
    __nv_bfloat16* Bl = (__nv_bfloat16*)(smem + SM_BL);

    const int tid = threadIdx.x, wid = tid >> 5, lane = tid & 31;
    const float* Xin = (in_sel == 0) ? Xext : ((in_sel == 1) ? g_bufA : g_bufB);
    const int row0 = blockIdx.x * 128;

    if (tid < 128) {
        bias_s[tid]       = bd[layer * DD + tid];
        bias_s[128 + tid] = bc[layer * DD + tid];
        bias_s[256 + tid] = bs[layer * DD + tid];
    }

    // ---- A conversion: fp32 -> bf16 hi/lo ----
    {
        int r  = tid >> 1;
        int c0 = (tid & 1) * 64;
        int gr = row0 + r;
        bool ok = gr < N;
        const float4* xp = (const float4*)(Xin + (size_t)gr * DD + c0);
        uint32_t* ah = (uint32_t*)&Ah[r * SA + c0];
        uint32_t* al = (uint32_t*)&Al[r * SA + c0];
#pragma unroll
        for (int c4 = 0; c4 < 16; c4++) {
            float4 v = ok ? __ldg(xp + c4) : make_float4(0.f, 0.f, 0.f, 0.f);
            __nv_bfloat162 h01 = __floats2bfloat162_rn(v.x, v.y);
            __nv_bfloat162 h23 = __floats2bfloat162_rn(v.z, v.w);
            float2 f01 = __bfloat1622float2(h01);
            float2 f23 = __bfloat1622float2(h23);
            __nv_bfloat162 l01 = __floats2bfloat162_rn(v.x - f01.x, v.y - f01.y);
            __nv_bfloat162 l23 = __floats2bfloat162_rn(v.z - f23.x, v.w - f23.y);
            uint32_t hp0, hp1, lp0, lp1;
            memcpy(&hp0, &h01, 4); memcpy(&hp1, &h23, 4);
            memcpy(&lp0, &l01, 4); memcpy(&lp1, &l23, 4);
            ah[c4 * 2] = hp0; ah[c4 * 2 + 1] = hp1;
            al[c4 * 2] = lp0; al[c4 * 2 + 1] = lp1;
        }
    }

    const int mrow = wid * 16;
    const int r    = lane >> 2;
    const int cc   = (lane & 3) * 2;

    for (int f = 0; f < 3; f++) {
        __syncthreads();                          // prior readers of B done
        copy_b(Bh, g_Wh[layer * 3 + f], tid);
        copy_b(Bl, g_Wl[layer * 3 + f], tid);
        __syncthreads();

        float acc[16][4];
#pragma unroll
        for (int nt = 0; nt < 16; nt++)
#pragma unroll
            for (int q = 0; q < 4; q++) acc[nt][q] = 0.f;

#pragma unroll
        for (int ks = 0; ks < 8; ks++) {
            const int kb = ks * 16;
            uint32_t a0h = *(const uint32_t*)&Ah[(mrow + r)     * SA + kb + cc];
            uint32_t a1h = *(const uint32_t*)&Ah[(mrow + r + 8) * SA + kb + cc];
            uint32_t a2h = *(const uint32_t*)&Ah[(mrow + r)     * SA + kb + cc + 8];
            uint32_t a3h = *(const uint32_t*)&Ah[(mrow + r + 8) * SA + kb + cc + 8];
            uint32_t a0l = *(const uint32_t*)&Al[(mrow + r)     * SA + kb + cc];
            uint32_t a1l = *(const uint32_t*)&Al[(mrow + r + 8) * SA + kb + cc];
            uint32_t a2l = *(const uint32_t*)&Al[(mrow + r)     * SA + kb + cc + 8];
            uint32_t a3l = *(const uint32_t*)&Al[(mrow + r + 8) * SA + kb + cc + 8];
#pragma unroll
            for (int nt = 0; nt < 16; nt++) {
                const int nb = (nt * 8 + r) * SA + kb + cc;
                uint32_t b0h = *(const uint32_t*)&Bh[nb];
                uint32_t b1h = *(const uint32_t*)&Bh[nb + 8];
                uint32_t b0l = *(const uint32_t*)&Bl[nb];
                uint32_t b1l = *(const uint32_t*)&Bl[nb + 8];
                MMA_BF16(acc[nt], a0h, a1h, a2h, a3h, b0h, b1h);
                MMA_BF16(acc[nt], a0h, a1h, a2h, a3h, b0l, b1l);
                MMA_BF16(acc[nt], a0l, a1l, a2l, a3l, b0h, b1h);
            }
        }

        // epilogue: +bias, float2 stores
        float* out = (f == 0) ? g_Xd : ((f == 1) ? g_Xc : g_self);
        const float* bv = bias_s + f * 128;
        int gr0 = row0 + mrow + r;
        int gr1 = gr0 + 8;
#pragma unroll
        for (int nt = 0; nt < 16; nt++) {
            int col = nt * 8 + cc;
            float bx = bv[col], by = bv[col + 1];
            if (gr0 < N)
                *(float2*)(out + (size_t)gr0 * DD + col) =
                    make_float2(acc[nt][0] + bx, acc[nt][1] + by);
            if (gr1 < N)
                *(float2*)(out + (size_t)gr1 * DD + col) =
                    make_float2(acc[nt][2] + bx, acc[nt][3] + by);
        }
    }
}

// ============================================================
// CSR build
// ============================================================
__global__ void zero_deg_kernel(int N)
{
    int i = blockIdx.x * blockDim.x + threadIdx.x;
    if (i <= N) g_deg[i] = 0;
}

__global__ void hist_kernel(const int* __restrict__ ei, int E)
{
    int e = blockIdx.x * blockDim.x + threadIdx.x;
    if (e < E) atomicAdd(&g_deg[ei[E + e]], 1);
}

__global__ void scan1_kernel(int N)
{
    __shared__ int s[256];
    int tid = threadIdx.x;
    int i = blockIdx.x * 256 + tid;
    int v = (i < N) ? g_deg[i] : 0;
    s[tid] = v;
    __syncthreads();
#pragma unroll
    for (int o = 1; o < 256; o <<= 1) {
        int t = (tid >= o) ? s[tid - o] : 0;
        __syncthreads();
        s[tid] += t;
        __syncthreads();
    }
    if (i < N) g_off[i] = s[tid] - v;
    if (tid == 255) g_bsum[blockIdx.x] = s[255];
}

__global__ void scan2_kernel(int nb)
{
    __shared__ int s[256];
    int tid = threadIdx.x;
    int v = (tid < nb) ? g_bsum[tid] : 0;
    s[tid] = v;
    __syncthreads();
#pragma unroll
    for (int o = 1; o < 256; o <<= 1) {
        int t = (tid >= o) ? s[tid - o] : 0;
        __syncthreads();
        s[tid] += t;
        __syncthreads();
    }
    if (tid < nb) g_bsum[tid] = s[tid] - v;
}

__global__ void scan3_kernel(int N, int E)
{
    int i = blockIdx.x * blockDim.x + threadIdx.x;
    if (i < N) {
        int o = g_off[i] + g_bsum[i >> 8];
        g_off[i] = o;
        g_cur[i] = o;
    }
    if (i == 0) g_off[N] = E;
}

__global__ void scatter_kernel(const int* __restrict__ ei,
                               const int* __restrict__ et, int E)
{
    int e = blockIdx.x * blockDim.x + threadIdx.x;
    if (e >= E) return;
    int src = ei[e];
    int dst = ei[E + e];
    int t   = et[e];
    int pos = atomicAdd(&g_cur[dst], 1);
    g_adj[pos] = src | (t << 31);
}

// ============================================================
// Aggregation (gather-only): one warp per dst node, MLP=4 (R5 loop).
// pool=1: relu result red.add'ed into pool output instead of buffer.
// ============================================================
__global__ __launch_bounds__(256) void agg_kernel(
    int N, int out_sel, int pool,
    const int* __restrict__ batch_ids, float* __restrict__ pout)
{
    int node = blockIdx.x * 8 + (threadIdx.x >> 5);
    int lane = threadIdx.x & 31;
    if (node >= N) return;

    int beg = g_off[node];
    int end = g_off[node + 1];

    float4 acc = *(const float4*)(g_self + (size_t)node * DD + lane * 4);

    for (int base = beg; base < end; base += 32) {
        int cnt = end - base; if (cnt > 32) cnt = 32;
        int idx = (base + lane < end) ? g_adj[base + lane] : 0;
        int q = 0;
        for (; q + 4 <= cnt; q += 4) {
            float4 v[4];
#pragma unroll
            for (int u = 0; u < 4; u++) {
                int p = __shfl_sync(0xffffffffu, idx, q + u);
                const float* bp = (p < 0) ? g_Xc : g_Xd;
                v[u] = *(const float4*)(bp + (size_t)(p & 0x7fffffff) * DD + lane * 4);
            }
#pragma unroll
            for (int u = 0; u < 4; u++) {
                acc.x += v[u].x; acc.y += v[u].y;
                acc.z += v[u].z; acc.w += v[u].w;
            }
        }
        for (; q < cnt; q++) {
            int p = __shfl_sync(0xffffffffu, idx, q);
            const float* bp = (p < 0) ? g_Xc : g_Xd;
            float4 v = *(const float4*)(bp + (size_t)(p & 0x7fffffff) * DD + lane * 4);
            acc.x += v.x; acc.y += v.y; acc.z += v.z; acc.w += v.w;
        }
    }

    acc.x = fmaxf(acc.x, 0.f); acc.y = fmaxf(acc.y, 0.f);
    acc.z = fmaxf(acc.z, 0.f); acc.w = fmaxf(acc.w, 0.f);

    if (pool) {
        int b = batch_ids[node];
        float* dp = pout + (size_t)b * DD + lane * 4;
        asm volatile("red.global.add.v4.f32 [%0], {%1,%2,%3,%4};"
                     :: "l"(dp), "f"(acc.x), "f"(acc.y), "f"(acc.z), "f"(acc.w)
                     : "memory");
    } else {
        float* out = (out_sel == 0) ? g_bufA : g_bufB;
        *(float4*)(out + (size_t)node * DD + lane * 4) = acc;
    }
}

// ============================================================
// Pooling support
// ============================================================
__global__ void zero_kernel(float* __restrict__ out, int out_size, int G)
{
    int i = blockIdx.x * blockDim.x + threadIdx.x;
    if (i < out_size) out[i] = 0.f;
    if (i < G) g_cnt[i] = 0.f;
}

__global__ void cnt_kernel(const int* __restrict__ batch_ids, int N)
{
    int i = blockIdx.x * blockDim.x + threadIdx.x;
    if (i < N) atomicAdd(&g_cnt[batch_ids[i]], 1.0f);
}

__global__ void pool_div_kernel(float* __restrict__ out, int out_size)
{
    int i = blockIdx.x * blockDim.x + threadIdx.x;
    if (i >= out_size) return;
    out[i] = out[i] / fmaxf(g_cnt[i >> 7], 1.0f);
}

// ============================================================
// launch  (gemm layer 0 placed 4th so ncu -s captures it)
// ============================================================
extern "C" void kernel_launch(void* const* d_in, const int* in_sizes, int n_in,
                              void* d_out, int out_size)
{
    const float* X   = (const float*)d_in[0];
    const float* Wd  = (const float*)d_in[1];
    const float* bd  = (const float*)d_in[2];
    const float* Wc  = (const float*)d_in[3];
    const float* bc  = (const float*)d_in[4];
    const float* Ws  = (const float*)d_in[5];
    const float* bs  = (const float*)d_in[6];
    const int*   ei  = (const int*)d_in[7];
    const int*   et  = (const int*)d_in[8];
    const int*   bid = (const int*)d_in[9];
    float* out = (float*)d_out;

    const int N = in_sizes[0] / DD;
    const int E = in_sizes[8];
    const int G = out_size / DD;

    static bool attr_done = false;
    if (!attr_done) {
        cudaFuncSetAttribute(gemm_mma_kernel,
                             cudaFuncAttributeMaxDynamicSharedMemorySize, SM_GTOT);
        attr_done = true;
    }

    int gtiles = (N + 127) / 128;
    int eblk  = (E + 255) / 256;
    int nwarp = (N + 7) / 8;
    int nb    = (N + 255) / 256;

    // ---- prep + CSR build; gemm0 is the 4th launch (ncu capture slot) ----
    prep_w_kernel<<<9, 128>>>(Wd, Wc, Ws);                       // 1
    zero_deg_kernel<<<(N + 256) / 256, 256>>>(N);                // 2
    hist_kernel<<<eblk, 256>>>(ei, E);                           // 3
    gemm_mma_kernel<<<gtiles, 256, SM_GTOT>>>(X, 0, 0, bd, bc, bs, N);  // 4 <- profiled
    scan1_kernel<<<nb, 256>>>(N);                                // 5
    scan2_kernel<<<1, 256>>>(nb);                                // 6
    scan3_kernel<<<nb, 256>>>(N, E);                             // 7
    scatter_kernel<<<eblk, 256>>>(ei, et, E);                    // 8
    zero_kernel<<<(out_size + G + 255) / 256, 256>>>(out, out_size, G);  // 9
    cnt_kernel<<<nb, 256>>>(bid, N);                             // 10

    // ---- layers ----
    agg_kernel<<<nwarp, 256>>>(N, 0, 0, bid, out);    // -> bufA

    gemm_mma_kernel<<<gtiles, 256, SM_GTOT>>>(X, 1, 1, bd, bc, bs, N);
    agg_kernel<<<nwarp, 256>>>(N, 1, 0, bid, out);    // -> bufB

    gemm_mma_kernel<<<gtiles, 256, SM_GTOT>>>(X, 2, 2, bd, bc, bs, N);
    agg_kernel<<<nwarp, 256>>>(N, 0, 1, bid, out);    // -> pooled into out

    pool_div_kernel<<<(out_size + 255) / 256, 256>>>(out, out_size);
}